// round 6
// baseline (speedup 1.0000x reference)
#include <cuda_runtime.h>

#define NB 256
#define NH 500
#define NI 784
#define NO 10
#define TT 200

#define V0F  2.1165347359575993f   // f32(eta^(eta/(eta-1))/(eta-1)), eta=4
#define SIGF 0.7788007830714049f   // f32(exp(-1/4))

typedef unsigned long long u64;

// static device scratch (allowed per harness rules)
__device__ float d_ann[NB*NH];
__device__ float d_cur[TT*NB*NH];        // 102.4 MB (cur2, reused for cur3)
__device__ float d_w2[TT*NB*NH];         // 102.4 MB
__device__ float d_w3[TT*NB*NO];         // 2 MB

__device__ __forceinline__ void ffma2(u64 &acc, u64 a, u64 b) {
    asm("fma.rn.f32x2 %0, %1, %2, %0;" : "+l"(acc) : "l"(a), "l"(b));
}
__device__ __forceinline__ float2 unpack2(u64 v) {
    float2 f; asm("mov.b64 {%0,%1}, %2;" : "=f"(f.x), "=f"(f.y) : "l"(v));
    return f;
}
__device__ __forceinline__ u64 dup2(float v) {
    u64 d; asm("mov.b64 %0, {%1, %1};" : "=l"(d) : "f"(v)); return d;
}

// XLA f32 tanh (rational approx, strict unfused) + logistic expansion
__device__ __forceinline__ float xla_tanh(float x) {
    const float xc = fminf(fmaxf(x, -7.90531110763549805f), 7.90531110763549805f);
    const float x2 = __fmul_rn(xc, xc);
    float p = -2.76076847742355e-16f;
    p = __fadd_rn(__fmul_rn(p, x2),  2.00018790482477e-13f);
    p = __fadd_rn(__fmul_rn(p, x2), -8.60467152213735e-11f);
    p = __fadd_rn(__fmul_rn(p, x2),  5.12229709037114e-08f);
    p = __fadd_rn(__fmul_rn(p, x2),  1.48572235717979e-05f);
    p = __fadd_rn(__fmul_rn(p, x2),  6.37261928875436e-04f);
    p = __fadd_rn(__fmul_rn(p, x2),  4.89352455891786e-03f);
    const float num = __fmul_rn(xc, p);
    float q = 1.19825839466702e-06f;
    q = __fadd_rn(__fmul_rn(q, x2), 1.18534705686654e-04f);
    q = __fadd_rn(__fmul_rn(q, x2), 2.26843463243900e-03f);
    q = __fadd_rn(__fmul_rn(q, x2), 4.89352518554385e-03f);
    const float t = __fdiv_rn(num, q);
    return (fabsf(x) < 0.0004f) ? x : t;
}
__device__ __forceinline__ float xla_logistic(float z) {
    return __fadd_rn(0.5f, __fmul_rn(0.5f, xla_tanh(__fmul_rn(0.5f, z))));
}

// ---------------------------------------------------------------------------
// Strict GEMM v2: C[m,n] = epi(chain_k fma(A[m,k],B[n,k]) + bias[n])
// A:[M,K] row-major, B:[N,K] row-major. Tile 128m x 64n x 8k, 256 threads,
// double-buffered, 3 CTAs/SM. Per output: single accumulator, k strictly
// ascending (bit-exact vs reference).
// grid = (n_panels, m_blocks): consecutive CTAs share the A tile (L2 reuse).
// Requires: M % 128 == 0, K % 4 == 0.
// ---------------------------------------------------------------------------
__global__ void __launch_bounds__(256, 3) gemm_strict_v2(
    const float* __restrict__ A, const float* __restrict__ B,
    const float* __restrict__ bias, float* __restrict__ C,
    int M, int N, int K, int act)
{
    __shared__ float As [2][8][132];   // [buf][k][m]
    __shared__ float Bs2[2][8][132];   // [buf][k][2n] duplicated pairs

    const int tid = threadIdx.x;
    const int tx  = tid & 15;          // compute n group (4 n each)
    const int ty  = tid >> 4;          // compute m group (8 m each)
    const int m0  = blockIdx.y * 128;
    const int j0  = blockIdx.x * 64;

    // loaders
    const int aLr = tid >> 1;              // 0..127
    const int aLc = (tid & 1) * 4;         // {0,4}
    const int bLr = tid >> 2;              // 0..63
    const int bLc = (tid & 3) * 2;         // {0,2,4,6}
    const bool bok_row = (j0 + bLr) < N;
    const int nblk = (K + 7) >> 3;

    u64 acc[4][4];
#pragma unroll
    for (int i = 0; i < 4; i++)
#pragma unroll
        for (int j = 0; j < 4; j++) acc[i][j] = 0ull;

    float4 ra; float2 rb;

    auto LD = [&](int blk) {
        const int kga = blk * 8 + aLc;
        const int kgb = blk * 8 + bLc;
        ra = (kga < K) ? *reinterpret_cast<const float4*>(&A[(size_t)(m0 + aLr) * K + kga])
                       : make_float4(0.f, 0.f, 0.f, 0.f);
        rb = (kgb < K && bok_row) ? *reinterpret_cast<const float2*>(&B[(size_t)(j0 + bLr) * K + kgb])
                                  : make_float2(0.f, 0.f);
    };
    auto ST = [&](int buf) {
        As[buf][aLc + 0][aLr] = ra.x;
        As[buf][aLc + 1][aLr] = ra.y;
        As[buf][aLc + 2][aLr] = ra.z;
        As[buf][aLc + 3][aLr] = ra.w;
        *reinterpret_cast<u64*>(&Bs2[buf][bLc + 0][2 * bLr]) = dup2(rb.x);
        *reinterpret_cast<u64*>(&Bs2[buf][bLc + 1][2 * bLr]) = dup2(rb.y);
    };

    LD(0); ST(0); __syncthreads();

    for (int blk = 0; blk < nblk; blk++) {
        const int buf = blk & 1;
        if (blk + 1 < nblk) LD(blk + 1);
#pragma unroll
        for (int k = 0; k < 8; k++) {
            const ulonglong2 a01 = *reinterpret_cast<const ulonglong2*>(&As[buf][k][ty * 8]);
            const ulonglong2 a23 = *reinterpret_cast<const ulonglong2*>(&As[buf][k][ty * 8 + 4]);
            const ulonglong2 b01 = *reinterpret_cast<const ulonglong2*>(&Bs2[buf][k][tx * 8]);
            const ulonglong2 b23 = *reinterpret_cast<const ulonglong2*>(&Bs2[buf][k][tx * 8 + 4]);
            const u64 a[4] = {a01.x, a01.y, a23.x, a23.y};
            const u64 b[4] = {b01.x, b01.y, b23.x, b23.y};
#pragma unroll
            for (int j = 0; j < 4; j++)
#pragma unroll
                for (int i = 0; i < 4; i++) ffma2(acc[i][j], a[i], b[j]);
        }
        if (blk + 1 < nblk) ST(buf ^ 1);
        __syncthreads();
    }

#pragma unroll
    for (int j = 0; j < 4; j++) {
        const int n = j0 + tx * 4 + j;
        if (n < N) {
            const float bn = bias[n];
#pragma unroll
            for (int i = 0; i < 4; i++) {
                const float2 f = unpack2(acc[i][j]);
                const int m = m0 + ty * 8 + 2 * i;
                float v0 = __fadd_rn(f.x, bn);
                float v1 = __fadd_rn(f.y, bn);
                if (act) { v0 = xla_logistic(v0); v1 = xla_logistic(v1); }
                C[(size_t)m * N + n] = v0;
                C[(size_t)(m + 1) * N + n] = v1;
            }
        }
    }
}

// ---- K2: cur2(t) for all t (IIR, no spike feedback; strict rounding) -------
__global__ void k2_cur2(const float* __restrict__ a1, const float* __restrict__ a2)
{
    const int idx = blockIdx.x * blockDim.x + threadIdx.x;
    if (idx >= NB * NH) return;
    const int j = idx % NH;
    const float c1 = a1[j], c2 = a2[j];
    const float va = __fmul_rn(V0F, d_ann[idx]);
    float p1 = 0.f, p2 = 0.f;
    for (int t = 0; t < TT; t++) {
        const float s = __fadd_rn(__fadd_rn(__fmul_rn(c1, p1), __fmul_rn(c2, p2)), va);
        d_cur[(size_t)t * NB * NH + idx] = s;
        p2 = p1; p1 = s;
    }
}

// ---- K45: fused layer-2 LIF + layer-3 IIR (strict; MLP-4 prefetch) ----------
__global__ void k45_lif2_cur3(const float* __restrict__ a1, const float* __restrict__ a2)
{
    const int idx = blockIdx.x * blockDim.x + threadIdx.x;
    if (idx >= NB * NH) return;
    const int j = idx % NH;
    const float c1 = a1[j], c2 = a2[j];
    float v = 0.f, ns = 1.f, p1 = 0.f, p2 = 0.f;
    for (int t0 = 0; t0 < TT; t0 += 4) {
        float w[4];
#pragma unroll
        for (int u = 0; u < 4; u++)
            w[u] = d_w2[(size_t)(t0 + u) * NB * NH + idx];
#pragma unroll
        for (int u = 0; u < 4; u++) {
            v = __fadd_rn(__fmul_rn(__fmul_rn(SIGF, v), ns), w[u]);
            const bool s = (__fadd_rn(v, -1.0f) > 0.f);
            ns = s ? 0.f : 1.f;
            const float inp = s ? V0F : 0.f;
            const float c = __fadd_rn(__fadd_rn(__fmul_rn(c1, p1), __fmul_rn(c2, p2)), inp);
            d_cur[(size_t)(t0 + u) * NB * NH + idx] = c;
            p2 = p1; p1 = c;
        }
    }
}

// ---- K6: w3 = cur3 @ W3^T + b3  (strict k-chain; float4 LDS) ----------------
__global__ void __launch_bounds__(640) k6_gemm3(const float* __restrict__ W3,
                                                const float* __restrict__ b3)
{
    __shared__ float W3s[NO * NH];   // 20 KB
    __shared__ float Cs[64][68];     // padded for float4 alignment
    const int tid = threadIdx.x;
    const int r0 = blockIdx.x * 64;
    for (int i = tid; i < NO * NH; i += 640) W3s[i] = W3[i];
    const int rr = tid / 10, o = tid - rr * 10;
    float acc = 0.f;
    for (int k0 = 0; k0 < NH; k0 += 64) {
        __syncthreads();
        for (int i = tid; i < 64 * 64; i += 640) {
            const int r = i >> 6, kq = i & 63, kg = k0 + kq;
            Cs[r][kq] = (kg < NH) ? d_cur[(size_t)(r0 + r) * NH + kg] : 0.f;
        }
        __syncthreads();
        const int kl = (NH - k0 < 64) ? (NH - k0) : 64;   // 64 or 52 (mult of 4)
        for (int k = 0; k < kl; k += 4) {
            const float4 c = *reinterpret_cast<const float4*>(&Cs[rr][k]);
            const float4 w = *reinterpret_cast<const float4*>(&W3s[o * NH + k0 + k]);
            acc = fmaf(c.x, w.x, acc);
            acc = fmaf(c.y, w.y, acc);
            acc = fmaf(c.z, w.z, acc);
            acc = fmaf(c.w, w.w, acc);
        }
    }
    d_w3[(size_t)(r0 + rr) * NO + o] = __fadd_rn(acc, b3[o]);
}

// ---- K7: layer-3 LIF scan -> output [B,10,T] --------------------------------
__global__ void k7_lif3(float* __restrict__ out)
{
    const int idx = blockIdx.x * blockDim.x + threadIdx.x;
    if (idx >= NB * NO) return;
    const int b = idx / NO, o = idx - b * NO;
    float v = 0.f, ns = 1.f;
    for (int t0 = 0; t0 < TT; t0 += 4) {
        float w[4];
#pragma unroll
        for (int u = 0; u < 4; u++)
            w[u] = d_w3[((size_t)(t0 + u) * NB + b) * NO + o];
#pragma unroll
        for (int u = 0; u < 4; u++) {
            v = __fadd_rn(__fmul_rn(__fmul_rn(SIGF, v), ns), w[u]);
            const bool s = (__fadd_rn(v, -1.0f) > 0.f);
            ns = s ? 0.f : 1.f;
            out[((size_t)b * NO + o) * TT + t0 + u] = s ? 1.f : 0.f;
        }
    }
}

// ---------------------------------------------------------------------------
extern "C" void kernel_launch(void* const* d_in, const int* in_sizes, int n_in,
                              void* d_out, int out_size)
{
    const float* inputs = (const float*)d_in[0];
    const float* W1     = (const float*)d_in[1];
    const float* b1     = (const float*)d_in[2];
    const float* a1_2   = (const float*)d_in[3];
    const float* a2_2   = (const float*)d_in[4];
    const float* W2     = (const float*)d_in[5];
    const float* b2     = (const float*)d_in[6];
    const float* a1_3   = (const float*)d_in[7];
    const float* a2_3   = (const float*)d_in[8];
    const float* W3     = (const float*)d_in[9];
    const float* b3     = (const float*)d_in[10];

    float* ann; cudaGetSymbolAddress((void**)&ann, d_ann);
    float* cur; cudaGetSymbolAddress((void**)&cur, d_cur);
    float* w2;  cudaGetSymbolAddress((void**)&w2,  d_w2);

    const int NRR = TT * NB;   // 51200

    // K1: ann = logistic(inputs @ W1^T + b1)     (M=256, K=784)
    gemm_strict_v2<<<dim3(8, NB / 128), 256>>>(inputs, W1, b1, ann, NB, NH, NI, 1);
    // K2: cur2 for all t
    k2_cur2<<<(NB * NH + 255) / 256, 256>>>(a1_2, a2_2);
    // K3: w2 = cur2_all @ W2^T + b2              (M=51200, K=500)
    gemm_strict_v2<<<dim3(8, NRR / 128), 256>>>(cur, W2, b2, w2, NRR, NH, NH, 0);
    // K45: layer-2 LIF + layer-3 synapse IIR (fused)
    k45_lif2_cur3<<<(NB * NH + 255) / 256, 256>>>(a1_3, a2_3);
    // K6: w3 = cur3_all @ W3^T + b3
    k6_gemm3<<<NRR / 64, 640>>>(W3, b3);
    // K7: layer-3 LIF -> output
    k7_lif3<<<(NB * NO + 255) / 256, 256>>>((float*)d_out);
}

// round 7
// speedup vs baseline: 1.3814x; 1.3814x over previous
#include <cuda_runtime.h>

#define NB 256
#define NH 500
#define NI 784
#define NO 10
#define TT 200

#define V0F  2.1165347359575993f   // f32(eta^(eta/(eta-1))/(eta-1)), eta=4
#define SIGF 0.7788007830714049f   // f32(exp(-1/4))

typedef unsigned long long u64;

// static device scratch (allowed per harness rules)
__device__ float d_ann[NB*NH];
__device__ float d_cur[TT*NB*NH];        // 102.4 MB (cur2, reused for cur3)
__device__ float d_w2[TT*NB*NH];         // 102.4 MB
__device__ float d_w3[TT*NB*NO];         // 2 MB

__device__ __forceinline__ void ffma2(u64 &acc, u64 a, u64 b) {
    asm("fma.rn.f32x2 %0, %1, %2, %0;" : "+l"(acc) : "l"(a), "l"(b));
}
__device__ __forceinline__ float2 unpack2(u64 v) {
    float2 f; asm("mov.b64 {%0,%1}, %2;" : "=f"(f.x), "=f"(f.y) : "l"(v));
    return f;
}
__device__ __forceinline__ u64 dup2(float v) {
    u64 d; asm("mov.b64 %0, {%1, %1};" : "=l"(d) : "f"(v)); return d;
}

// XLA f32 tanh (rational approx, strict unfused) + logistic expansion
__device__ __forceinline__ float xla_tanh(float x) {
    const float xc = fminf(fmaxf(x, -7.90531110763549805f), 7.90531110763549805f);
    const float x2 = __fmul_rn(xc, xc);
    float p = -2.76076847742355e-16f;
    p = __fadd_rn(__fmul_rn(p, x2),  2.00018790482477e-13f);
    p = __fadd_rn(__fmul_rn(p, x2), -8.60467152213735e-11f);
    p = __fadd_rn(__fmul_rn(p, x2),  5.12229709037114e-08f);
    p = __fadd_rn(__fmul_rn(p, x2),  1.48572235717979e-05f);
    p = __fadd_rn(__fmul_rn(p, x2),  6.37261928875436e-04f);
    p = __fadd_rn(__fmul_rn(p, x2),  4.89352455891786e-03f);
    const float num = __fmul_rn(xc, p);
    float q = 1.19825839466702e-06f;
    q = __fadd_rn(__fmul_rn(q, x2), 1.18534705686654e-04f);
    q = __fadd_rn(__fmul_rn(q, x2), 2.26843463243900e-03f);
    q = __fadd_rn(__fmul_rn(q, x2), 4.89352518554385e-03f);
    const float t = __fdiv_rn(num, q);
    return (fabsf(x) < 0.0004f) ? x : t;
}
__device__ __forceinline__ float xla_logistic(float z) {
    return __fadd_rn(0.5f, __fmul_rn(0.5f, xla_tanh(__fmul_rn(0.5f, z))));
}

// ---------------------------------------------------------------------------
// Strict GEMM v3: C[m,n] = epi(chain_k fma(A[m,k],B[n,k]) + bias[n])
// A:[M,K] row-major, B:[N,K] row-major. Tile 128m x 128n x 8k, 256 threads,
// double-buffered. Thread tile 8m x 8n; accumulator lanes pair (n, n+1) so B
// is read as natural f32 pairs (no smem duplication); A is dup'd in registers.
// Per output: single accumulator, strictly k-ascending fma.rn chain.
// Requires: M % 128 == 0, rows 16B-aligned (K % 4 == 0).
// ---------------------------------------------------------------------------
__global__ void __launch_bounds__(256, 2) gemm_strict_v3(
    const float* __restrict__ A, const float* __restrict__ B,
    const float* __restrict__ bias, float* __restrict__ C,
    int M, int N, int K, int act)
{
    __shared__ float As[2][8][132];   // [buf][k][m]
    __shared__ float Bs[2][8][132];   // [buf][k][n]

    const int tid = threadIdx.x;
    const int tx  = tid & 15;          // n group: 8 n each
    const int ty  = tid >> 4;          // m group: 8 m each
    const int m0  = blockIdx.y * 128;
    const int j0  = blockIdx.x * 128;

    const int lr = tid >> 1;           // loader row 0..127
    const int lc = (tid & 1) * 4;      // loader k chunk {0,4}
    const bool bok = (j0 + lr) < N;
    const int nblk = (K + 7) >> 3;

    u64 acc[8][4];
#pragma unroll
    for (int i = 0; i < 8; i++)
#pragma unroll
        for (int j = 0; j < 4; j++) acc[i][j] = 0ull;

    float4 ra, rb;
    const float4 z4 = make_float4(0.f, 0.f, 0.f, 0.f);

    auto LD = [&](int blk) {
        const int kg = blk * 8 + lc;
        const bool kok = kg < K;
        ra = kok ? *reinterpret_cast<const float4*>(&A[(size_t)(m0 + lr) * K + kg]) : z4;
        rb = (kok && bok) ? *reinterpret_cast<const float4*>(&B[(size_t)(j0 + lr) * K + kg]) : z4;
    };
    auto ST = [&](int buf) {
        As[buf][lc + 0][lr] = ra.x;  As[buf][lc + 1][lr] = ra.y;
        As[buf][lc + 2][lr] = ra.z;  As[buf][lc + 3][lr] = ra.w;
        Bs[buf][lc + 0][lr] = rb.x;  Bs[buf][lc + 1][lr] = rb.y;
        Bs[buf][lc + 2][lr] = rb.z;  Bs[buf][lc + 3][lr] = rb.w;
    };

    LD(0); ST(0); __syncthreads();

    for (int blk = 0; blk < nblk; blk++) {
        const int buf = blk & 1;
        if (blk + 1 < nblk) LD(blk + 1);
#pragma unroll
        for (int k = 0; k < 8; k++) {
            const float4 a0 = *reinterpret_cast<const float4*>(&As[buf][k][ty * 8]);
            const float4 a1 = *reinterpret_cast<const float4*>(&As[buf][k][ty * 8 + 4]);
            u64 ad[8];
            ad[0] = dup2(a0.x); ad[1] = dup2(a0.y); ad[2] = dup2(a0.z); ad[3] = dup2(a0.w);
            ad[4] = dup2(a1.x); ad[5] = dup2(a1.y); ad[6] = dup2(a1.z); ad[7] = dup2(a1.w);
            const ulonglong2 b01 = *reinterpret_cast<const ulonglong2*>(&Bs[buf][k][tx * 8]);
            const ulonglong2 b23 = *reinterpret_cast<const ulonglong2*>(&Bs[buf][k][tx * 8 + 4]);
            const u64 b[4] = {b01.x, b01.y, b23.x, b23.y};
#pragma unroll
            for (int mi = 0; mi < 8; mi++)
#pragma unroll
                for (int nj = 0; nj < 4; nj++) ffma2(acc[mi][nj], ad[mi], b[nj]);
        }
        if (blk + 1 < nblk) ST(buf ^ 1);
        __syncthreads();
    }

#pragma unroll
    for (int mi = 0; mi < 8; mi++) {
        const int m = m0 + ty * 8 + mi;
#pragma unroll
        for (int nj = 0; nj < 4; nj++) {
            const int n = j0 + tx * 8 + 2 * nj;
            if (n < N) {
                const float2 f = unpack2(acc[mi][nj]);
                float v0 = __fadd_rn(f.x, bias[n]);
                if (act) v0 = xla_logistic(v0);
                C[(size_t)m * N + n] = v0;
                if (n + 1 < N) {
                    float v1 = __fadd_rn(f.y, bias[n + 1]);
                    if (act) v1 = xla_logistic(v1);
                    C[(size_t)m * N + n + 1] = v1;
                }
            }
        }
    }
}

// ---- K2: cur2(t) for all t (IIR, no spike feedback; strict rounding) -------
__global__ void k2_cur2(const float* __restrict__ a1, const float* __restrict__ a2)
{
    const int idx = blockIdx.x * blockDim.x + threadIdx.x;
    if (idx >= NB * NH) return;
    const int j = idx % NH;
    const float c1 = a1[j], c2 = a2[j];
    const float va = __fmul_rn(V0F, d_ann[idx]);
    float p1 = 0.f, p2 = 0.f;
    for (int t = 0; t < TT; t++) {
        const float s = __fadd_rn(__fadd_rn(__fmul_rn(c1, p1), __fmul_rn(c2, p2)), va);
        d_cur[(size_t)t * NB * NH + idx] = s;
        p2 = p1; p1 = s;
    }
}

// ---- K45: fused layer-2 LIF + layer-3 IIR (strict; MLP-4 prefetch) ----------
__global__ void k45_lif2_cur3(const float* __restrict__ a1, const float* __restrict__ a2)
{
    const int idx = blockIdx.x * blockDim.x + threadIdx.x;
    if (idx >= NB * NH) return;
    const int j = idx % NH;
    const float c1 = a1[j], c2 = a2[j];
    float v = 0.f, ns = 1.f, p1 = 0.f, p2 = 0.f;
    for (int t0 = 0; t0 < TT; t0 += 4) {
        float w[4];
#pragma unroll
        for (int u = 0; u < 4; u++)
            w[u] = d_w2[(size_t)(t0 + u) * NB * NH + idx];
#pragma unroll
        for (int u = 0; u < 4; u++) {
            v = __fadd_rn(__fmul_rn(__fmul_rn(SIGF, v), ns), w[u]);
            const bool s = (__fadd_rn(v, -1.0f) > 0.f);
            ns = s ? 0.f : 1.f;
            const float inp = s ? V0F : 0.f;
            const float c = __fadd_rn(__fadd_rn(__fmul_rn(c1, p1), __fmul_rn(c2, p2)), inp);
            d_cur[(size_t)(t0 + u) * NB * NH + idx] = c;
            p2 = p1; p1 = c;
        }
    }
}

// ---- K6: w3 = cur3 @ W3^T + b3  (strict k-chain; float4 LDS) ----------------
__global__ void __launch_bounds__(640) k6_gemm3(const float* __restrict__ W3,
                                                const float* __restrict__ b3)
{
    __shared__ float W3s[NO * NH];   // 20 KB
    __shared__ float Cs[64][68];     // padded for float4 alignment
    const int tid = threadIdx.x;
    const int r0 = blockIdx.x * 64;
    for (int i = tid; i < NO * NH; i += 640) W3s[i] = W3[i];
    const int rr = tid / 10, o = tid - rr * 10;
    float acc = 0.f;
    for (int k0 = 0; k0 < NH; k0 += 64) {
        __syncthreads();
        for (int i = tid; i < 64 * 64; i += 640) {
            const int r = i >> 6, kq = i & 63, kg = k0 + kq;
            Cs[r][kq] = (kg < NH) ? d_cur[(size_t)(r0 + r) * NH + kg] : 0.f;
        }
        __syncthreads();
        const int kl = (NH - k0 < 64) ? (NH - k0) : 64;   // 64 or 52 (mult of 4)
        for (int k = 0; k < kl; k += 4) {
            const float4 c = *reinterpret_cast<const float4*>(&Cs[rr][k]);
            const float4 w = *reinterpret_cast<const float4*>(&W3s[o * NH + k0 + k]);
            acc = fmaf(c.x, w.x, acc);
            acc = fmaf(c.y, w.y, acc);
            acc = fmaf(c.z, w.z, acc);
            acc = fmaf(c.w, w.w, acc);
        }
    }
    d_w3[(size_t)(r0 + rr) * NO + o] = __fadd_rn(acc, b3[o]);
}

// ---- K7: layer-3 LIF scan -> output [B,10,T] --------------------------------
__global__ void k7_lif3(float* __restrict__ out)
{
    const int idx = blockIdx.x * blockDim.x + threadIdx.x;
    if (idx >= NB * NO) return;
    const int b = idx / NO, o = idx - b * NO;
    float v = 0.f, ns = 1.f;
    for (int t0 = 0; t0 < TT; t0 += 4) {
        float w[4];
#pragma unroll
        for (int u = 0; u < 4; u++)
            w[u] = d_w3[((size_t)(t0 + u) * NB + b) * NO + o];
#pragma unroll
        for (int u = 0; u < 4; u++) {
            v = __fadd_rn(__fmul_rn(__fmul_rn(SIGF, v), ns), w[u]);
            const bool s = (__fadd_rn(v, -1.0f) > 0.f);
            ns = s ? 0.f : 1.f;
            out[((size_t)b * NO + o) * TT + t0 + u] = s ? 1.f : 0.f;
        }
    }
}

// ---------------------------------------------------------------------------
extern "C" void kernel_launch(void* const* d_in, const int* in_sizes, int n_in,
                              void* d_out, int out_size)
{
    const float* inputs = (const float*)d_in[0];
    const float* W1     = (const float*)d_in[1];
    const float* b1     = (const float*)d_in[2];
    const float* a1_2   = (const float*)d_in[3];
    const float* a2_2   = (const float*)d_in[4];
    const float* W2     = (const float*)d_in[5];
    const float* b2     = (const float*)d_in[6];
    const float* a1_3   = (const float*)d_in[7];
    const float* a2_3   = (const float*)d_in[8];
    const float* W3     = (const float*)d_in[9];
    const float* b3     = (const float*)d_in[10];

    float* ann; cudaGetSymbolAddress((void**)&ann, d_ann);
    float* cur; cudaGetSymbolAddress((void**)&cur, d_cur);
    float* w2;  cudaGetSymbolAddress((void**)&w2,  d_w2);

    const int NRR = TT * NB;   // 51200

    // K1: ann = logistic(inputs @ W1^T + b1)     (M=256, K=784)
    gemm_strict_v3<<<dim3(4, NB / 128), 256>>>(inputs, W1, b1, ann, NB, NH, NI, 1);
    // K2: cur2 for all t
    k2_cur2<<<(NB * NH + 255) / 256, 256>>>(a1_2, a2_2);
    // K3: w2 = cur2_all @ W2^T + b2              (M=51200, K=500)
    gemm_strict_v3<<<dim3(4, NRR / 128), 256>>>(cur, W2, b2, w2, NRR, NH, NH, 0);
    // K45: layer-2 LIF + layer-3 synapse IIR (fused)
    k45_lif2_cur3<<<(NB * NH + 255) / 256, 256>>>(a1_3, a2_3);
    // K6: w3 = cur3_all @ W3^T + b3
    k6_gemm3<<<NRR / 64, 640>>>(W3, b3);
    // K7: layer-3 LIF -> output
    k7_lif3<<<(NB * NO + 255) / 256, 256>>>((float*)d_out);
}